// round 8
// baseline (speedup 1.0000x reference)
#include <cuda_runtime.h>

// Problem constants
#define Bc     32
#define Ic     1152
#define Oc     10
#define Dc     16
#define Hc     10
#define Sc     922
#define HALF_I 576
#define ROW    20          // padded row stride (floats), 16B-aligned
#define NPAIR  (Bc * Oc)   // 320
#define NCHUNK 9           // K2 loss chunks of 128 rows

// Inter-kernel scratch
// g_part[pair][half][slot][17]: slot0 = T/N of half; slot 1+h = C_h/c_h of half
__device__ float    g_part[NPAIR][2][11][17];
// g_bm[pair][h][36]: 1152-bit sampled-row mask per hypothesis
__device__ unsigned g_bm[NPAIR][Hc][36];
// g_loss[pair][chunk][h]: partial losses
__device__ float    g_loss[NPAIR][NCHUNK][Hc];

// K1 dynamic smem: u_s 576*20 f | vnS 576 f | red 8*17 f | bm 180 u32
#define K1_SMEM ((HALF_I*ROW + HALF_I + 8*17 + 180) * 4)

__device__ __forceinline__ float sqrt_approx(float x) {
    float r; asm("sqrt.approx.f32 %0, %1;" : "=f"(r) : "f"(x)); return r;
}

__device__ __forceinline__ void load_row(const float* __restrict__ rp, float f[16]) {
    float4 a = *(const float4*)(rp + 0);
    float4 b = *(const float4*)(rp + 4);
    float4 c = *(const float4*)(rp + 8);
    float4 d = *(const float4*)(rp + 12);
    f[0]=a.x; f[1]=a.y; f[2]=a.z;  f[3]=a.w;
    f[4]=b.x; f[5]=b.y; f[6]=b.z;  f[7]=b.w;
    f[8]=c.x; f[9]=c.y; f[10]=c.z; f[11]=c.w;
    f[12]=d.x; f[13]=d.y; f[14]=d.z; f[15]=d.w;
}

// ===================== K0: sidx stream -> bitmaps ==========================
extern "C" __global__ void __launch_bounds__(256)
k0_bitmap(const unsigned int* __restrict__ sidx_raw)
{
    __shared__ unsigned bm[Hc * 36];
    __shared__ int det;

    const int o    = blockIdx.x;
    const int b    = blockIdx.y;
    const int pair = b * Oc + o;
    const int tid  = threadIdx.x;
    const int lane = tid & 31;

    // FIX (R7 NaN): cover the FULL 360-word extent with 256 threads
    for (int t = tid; t < Hc * 36; t += 256) bm[t] = 0u;

    // dtype detect: int64 <=> odd 32-bit words of first 128 elems all zero
    if (tid < 32) {
        unsigned a = 0;
        #pragma unroll
        for (int j = 0; j < 4; j++) a |= sidx_raw[2 * (lane * 4 + j) + 1];
        unsigned bal = __ballot_sync(0xffffffffu, a != 0);
        if (lane == 0) det = (bal == 0) ? 1 : 0;
    }
    __syncthreads();
    const bool is64 = (det != 0);

    const size_t sbase = (((size_t)b * Sc) * Oc + o) * Hc;
    #pragma unroll 4
    for (int k = 0; k < 37; k++) {
        int t = tid + k * 256;
        if (t < Sc * Hc) {
            int s = (int)(((unsigned)t * 52429u) >> 19);   // t/10
            int h = t - s * 10;
            size_t off = sbase + (size_t)s * (Oc * Hc) + h;
            unsigned v = is64 ? __ldg(sidx_raw + off * 2) : __ldg(sidx_raw + off);
            atomicOr(&bm[h * 36 + (v >> 5)], 1u << (v & 31));
        }
    }
    __syncthreads();

    // FIX (R7 NaN): write out all 360 words
    for (int t = tid; t < Hc * 36; t += 256)
        g_bm[pair][t / 36][t % 36] = bm[t];
}

// ============================ K1: partial sums ==============================
extern "C" __global__ void __launch_bounds__(256, 4)
k1_partials(const float* __restrict__ u)
{
    extern __shared__ float sm[];
    float*    u_s = sm;                       // [HALF_I][ROW]
    float*    vnS = u_s + HALF_I * ROW;       // [HALF_I]
    float*    red = vnS + HALF_I;             // [8][17]
    unsigned* bm  = (unsigned*)(red + 8*17);  // [Hc][18] mask words of THIS half

    const int o    = blockIdx.x;
    const int b    = blockIdx.y;
    const int half = blockIdx.z;
    const int pair = b * Oc + o;
    const int i0   = half * HALF_I;
    const int tid  = threadIdx.x;
    const int w    = tid >> 5;
    const int lane = tid & 31;

    // bitmap slice for this half (L2-hot from K0); 180 < 256 threads, one shot
    if (tid < Hc * 18)
        bm[tid] = g_bm[pair][tid / 18][half * 18 + tid % 18];

    // stage this half's u rows (coalesced float4)
    {
        const float4* gp = (const float4*)u + ((size_t)((size_t)b * Ic + i0) * Oc + o) * 4;
        #pragma unroll
        for (int k = 0; k < 9; k++) {
            int t = tid + k * 256;
            if (t < HALF_I * 4) {
                int i = t >> 2, q = t & 3;
                float4 v = __ldg(gp + (size_t)i * (Oc * 4) + q);
                *(float4*)&u_s[i * ROW + q * 4] = v;
            }
        }
    }
    __syncthreads();

    // norms + T/N partials over this half
    {
        float tA[17];
        #pragma unroll
        for (int j = 0; j < 17; j++) tA[j] = 0.f;

        #pragma unroll
        for (int k = 0; k < 3; k++) {
            int i = tid + k * 256;
            if (i < HALF_I) {
                float f[16];
                load_row(&u_s[i * ROW], f);
                float ss = 0.f;
                #pragma unroll
                for (int d = 0; d < Dc; d++) ss = fmaf(f[d], f[d], ss);
                float vn = sqrt_approx(ss);
                vnS[i] = vn;
                tA[16] += vn;
                #pragma unroll
                for (int d = 0; d < Dc; d++) tA[d] = fmaf(vn, f[d], tA[d]);
            }
        }
        #pragma unroll
        for (int off = 16; off; off >>= 1)
            #pragma unroll
            for (int j = 0; j < 17; j++)
                tA[j] += __shfl_down_sync(0xffffffffu, tA[j], off);
        if (lane == 0) {
            #pragma unroll
            for (int j = 0; j < 17; j++) red[w * 17 + j] = tA[j];
        }
    }
    __syncthreads();

    if (tid < 17) {
        float s = 0.f;
        #pragma unroll
        for (int ww = 0; ww < 8; ww++) s += red[ww * 17 + tid];
        g_part[pair][half][0][tid] = s;
    }

    // complement gather: warp w -> h = w; warps 0,1 also h = 8,9
    #pragma unroll
    for (int rep = 0; rep < 2; rep++) {
        int hh = w + rep * 8;
        if (hh < Hc) {
            float cA[17];
            #pragma unroll
            for (int j = 0; j < 17; j++) cA[j] = 0.f;

            #pragma unroll 3
            for (int wd = 0; wd < 18; wd++) {
                unsigned bits = bm[hh * 18 + wd];        // broadcast LDS
                if (!((bits >> lane) & 1u)) {            // complement bit
                    int i = wd * 32 + lane;
                    float f[16];
                    load_row(&u_s[i * ROW], f);
                    float vn = vnS[i];                   // identical to T-pass value
                    cA[16] += vn;
                    #pragma unroll
                    for (int d = 0; d < Dc; d++) cA[d] = fmaf(vn, f[d], cA[d]);
                }
            }
            #pragma unroll
            for (int off = 16; off; off >>= 1)
                #pragma unroll
                for (int j = 0; j < 17; j++)
                    cA[j] += __shfl_down_sync(0xffffffffu, cA[j], off);
            if (lane == 0) {
                #pragma unroll
                for (int j = 0; j < 17; j++) g_part[pair][half][1 + hh][j] = cA[j];
            }
        }
    }
}

// ==================== K2: per-chunk partial losses ==========================
extern "C" __global__ void __launch_bounds__(256, 4)
k2_loss(const float* __restrict__ u)
{
    __shared__ float u_c[128 * ROW];
    __shared__ float mu[Hc * Dc];
    __shared__ float mm[Hc];
    __shared__ float red[8 * 5];

    const int o    = blockIdx.x;
    const int b    = blockIdx.y;
    const int ch   = blockIdx.z;
    const int pair = b * Oc + o;
    const int tid  = threadIdx.x;
    const int w    = tid >> 5;
    const int lane = tid & 31;
    const int r    = tid & 127;
    const int g    = tid >> 7;        // 0 -> h 0..4, 1 -> h 5..9

    // Mu[h][d] = (T - C_h) / (N - c_h)   (fixed order -> same value in every CTA)
    if (tid < Hc * Dc) {
        int h = tid >> 4, d = tid & 15;
        float T = g_part[pair][0][0][d]      + g_part[pair][1][0][d];
        float N = g_part[pair][0][0][16]     + g_part[pair][1][0][16];
        float C = g_part[pair][0][1 + h][d]  + g_part[pair][1][1 + h][d];
        float c = g_part[pair][0][1 + h][16] + g_part[pair][1][1 + h][16];
        mu[tid] = (T - C) / (N - c);
    }
    // stage this 128-row chunk
    {
        const float4* gp = (const float4*)u + ((size_t)((size_t)b * Ic) * Oc + o) * 4;
        #pragma unroll
        for (int k = 0; k < 2; k++) {
            int t = tid + k * 256;
            int i = t >> 2, q = t & 3;
            float4 v = __ldg(gp + (size_t)(ch * 128 + i) * (Oc * 4) + q);
            *(float4*)&u_c[i * ROW + q * 4] = v;
        }
    }
    __syncthreads();
    if (tid < Hc) {
        float s = 0.f;
        #pragma unroll
        for (int d = 0; d < Dc; d++) s = fmaf(mu[tid * 16 + d], mu[tid * 16 + d], s);
        mm[tid] = s;
    }
    __syncthreads();

    // losses: ||u - mu||^2 = ||u||^2 - 2 u.mu + ||mu||^2
    float pl[5] = {0.f, 0.f, 0.f, 0.f, 0.f};
    {
        float f[16];
        load_row(&u_c[r * ROW], f);
        float ss = 0.f;
        #pragma unroll
        for (int d = 0; d < Dc; d++) ss = fmaf(f[d], f[d], ss);

        #pragma unroll
        for (int j = 0; j < 5; j++) {
            int h = g * 5 + j;
            const float4* mp = (const float4*)&mu[h * 16];   // broadcast LDS.128
            float4 m0 = mp[0], m1 = mp[1], m2 = mp[2], m3 = mp[3];
            float dot = 0.f;
            dot = fmaf(f[0],  m0.x, dot); dot = fmaf(f[1],  m0.y, dot);
            dot = fmaf(f[2],  m0.z, dot); dot = fmaf(f[3],  m0.w, dot);
            dot = fmaf(f[4],  m1.x, dot); dot = fmaf(f[5],  m1.y, dot);
            dot = fmaf(f[6],  m1.z, dot); dot = fmaf(f[7],  m1.w, dot);
            dot = fmaf(f[8],  m2.x, dot); dot = fmaf(f[9],  m2.y, dot);
            dot = fmaf(f[10], m2.z, dot); dot = fmaf(f[11], m2.w, dot);
            dot = fmaf(f[12], m3.x, dot); dot = fmaf(f[13], m3.y, dot);
            dot = fmaf(f[14], m3.z, dot); dot = fmaf(f[15], m3.w, dot);
            float val = fmaf(-2.f, dot, ss + mm[h]);
            pl[j] += sqrt_approx(fmaxf(val, 0.f));
        }
    }
    #pragma unroll
    for (int off = 16; off; off >>= 1)
        #pragma unroll
        for (int j = 0; j < 5; j++)
            pl[j] += __shfl_down_sync(0xffffffffu, pl[j], off);
    if (lane == 0) {
        #pragma unroll
        for (int j = 0; j < 5; j++) red[w * 5 + j] = pl[j];
    }
    __syncthreads();

    if (tid < Hc) {
        int g2 = tid / 5, j = tid - g2 * 5;
        float s = 0.f;
        #pragma unroll
        for (int ww = 0; ww < 4; ww++) s += red[(g2 * 4 + ww) * 5 + j];
        g_loss[pair][ch][tid] = s;
    }
}

// ============== K3: combine losses, argmin, emit Mu[h*] =====================
extern "C" __global__ void __launch_bounds__(32)
k3_emit(float* __restrict__ out)
{
    const int pair = blockIdx.x;
    const int lane = threadIdx.x;

    float L = 3.0e38f;
    if (lane < Hc) {
        float s = 0.f;
        #pragma unroll
        for (int c = 0; c < NCHUNK; c++) s += g_loss[pair][c][lane];
        L = s;
    }
    // first-occurrence argmin across lanes 0..9 (all lanes compute same result)
    int hm = 0;
    float best = __shfl_sync(0xffffffffu, L, 0);
    #pragma unroll
    for (int h = 1; h < Hc; h++) {
        float v = __shfl_sync(0xffffffffu, L, h);
        if (v < best) { best = v; hm = h; }
    }
    if (lane < Dc) {
        float T = g_part[pair][0][0][lane]      + g_part[pair][1][0][lane];
        float N = g_part[pair][0][0][16]        + g_part[pair][1][0][16];
        float C = g_part[pair][0][1 + hm][lane] + g_part[pair][1][1 + hm][lane];
        float c = g_part[pair][0][1 + hm][16]   + g_part[pair][1][1 + hm][16];
        out[(size_t)pair * Dc + lane] = (T - C) / (N - c);
    }
}

extern "C" void kernel_launch(void* const* d_in, const int* in_sizes, int n_in,
                              void* d_out, int out_size)
{
    const float*        u    = (const float*)d_in[0];
    const unsigned int* sidx = (const unsigned int*)d_in[1];
    float*              out  = (float*)d_out;

    cudaFuncSetAttribute(k1_partials,
                         cudaFuncAttributeMaxDynamicSharedMemorySize, K1_SMEM);

    k0_bitmap<<<dim3(Oc, Bc), 256>>>(sidx);
    k1_partials<<<dim3(Oc, Bc, 2), 256, K1_SMEM>>>(u);
    k2_loss<<<dim3(Oc, Bc, NCHUNK), 256>>>(u);
    k3_emit<<<NPAIR, 32>>>(out);
}

// round 10
// speedup vs baseline: 1.1364x; 1.1364x over previous
#include <cuda_runtime.h>

// Problem constants
#define Bc     32
#define Ic     1152
#define Oc     10
#define Dc     16
#define Hc     10
#define Sc     922
#define NPAIR  (Bc * Oc)   // 320
#define NCHUNK 9           // K2: 9 chunks x 128 rows
#define K1_THR 512
#define K2_THR 128

// Inter-kernel scratch
// g_part[pair][slot][17]: slot 0 = T[0..15],N ; slot 1+h = C_h[0..15],c_h
__device__ float g_part[NPAIR][11][17];
// g_loss[pair][chunk][h]
__device__ float g_loss[NPAIR][NCHUNK][Hc];
// completion counters (zero-init; reset by last CTA each launch)
__device__ int   g_sem[NPAIR];

__device__ __forceinline__ float sqrt_approx(float x) {
    float r; asm("sqrt.approx.f32 %0, %1;" : "=f"(r) : "f"(x)); return r;
}

// Direct global row load: 64B-aligned, 2 perfectly-used 32B sectors.
__device__ __forceinline__ void load_row_g(const float4* __restrict__ gp,
                                           int i, float f[16]) {
    float4 a = __ldg(gp + (size_t)i * 40 + 0);
    float4 b = __ldg(gp + (size_t)i * 40 + 1);
    float4 c = __ldg(gp + (size_t)i * 40 + 2);
    float4 d = __ldg(gp + (size_t)i * 40 + 3);
    f[0]=a.x; f[1]=a.y; f[2]=a.z;  f[3]=a.w;
    f[4]=b.x; f[5]=b.y; f[6]=b.z;  f[7]=b.w;
    f[8]=c.x; f[9]=c.y; f[10]=c.z; f[11]=c.w;
    f[12]=d.x; f[13]=d.y; f[14]=d.z; f[15]=d.w;
}

// ============ K1: bitmap + T/N + complement sums (one CTA per pair) ========
extern "C" __global__ void __launch_bounds__(K1_THR, 2)
k1_partials(const float* __restrict__ u, const unsigned int* __restrict__ sidx_raw)
{
    __shared__ unsigned bm[Hc * 36];     // 1152-bit sampled mask per h
    __shared__ float    red[16 * 17];    // T/N warp partials
    __shared__ float    red2[20 * 17];   // complement job partials
    __shared__ int      det;

    const int o    = blockIdx.x;
    const int b    = blockIdx.y;
    const int pair = b * Oc + o;
    const int tid  = threadIdx.x;
    const int w    = tid >> 5;
    const int lane = tid & 31;

    if (tid < Hc * 36) bm[tid] = 0u;     // 360 < 512: one shot
    // dtype detect: int64 <=> odd 32-bit words of first 128 elems all zero
    if (w == 0) {
        unsigned a = 0;
        #pragma unroll
        for (int j = 0; j < 4; j++) a |= __ldg(sidx_raw + 2 * (lane * 4 + j) + 1);
        unsigned bal = __ballot_sync(0xffffffffu, a != 0);
        if (lane == 0) det = (bal == 0) ? 1 : 0;
    }
    __syncthreads();
    const bool is64 = (det != 0);

    // ---- sidx scan (single read) -> bitmap --------------------------------
    // FIX (R9): 19 iterations; 18*512=9216 < Sc*Hc=9220 dropped the last 4
    // samples and corrupted C_h for h=6..9 (rel_err 0.12).
    {
        const size_t sbase = (((size_t)b * Sc) * Oc + o) * Hc;
        const uint2* p64 = (const uint2*)sidx_raw;
        #pragma unroll 3
        for (int k = 0; k < 19; k++) {
            int t = tid + k * K1_THR;
            if (t < Sc * Hc) {
                int s = (int)(((unsigned)t * 52429u) >> 19);   // t/10
                int h = t - s * 10;
                size_t off = sbase + (size_t)s * 100 + h;
                unsigned v = is64 ? __ldg(&p64[off]).x : __ldg(sidx_raw + off);
                atomicOr(&bm[h * 36 + (v >> 5)], 1u << (v & 31));
            }
        }
    }

    const float4* gp = (const float4*)u + ((size_t)b * Ic * Oc + o) * 4;

    // ---- T/N streaming pass (thread-per-row, sector-perfect LDG) ----------
    {
        float tA[17];
        #pragma unroll
        for (int j = 0; j < 17; j++) tA[j] = 0.f;
        #pragma unroll
        for (int k = 0; k < 3; k++) {
            int i = tid + k * K1_THR;
            if (i < Ic) {
                float f[16];
                load_row_g(gp, i, f);
                float ss = 0.f;
                #pragma unroll
                for (int d = 0; d < Dc; d++) ss = fmaf(f[d], f[d], ss);
                float vn = sqrt_approx(ss);
                tA[16] += vn;
                #pragma unroll
                for (int d = 0; d < Dc; d++) tA[d] = fmaf(vn, f[d], tA[d]);
            }
        }
        #pragma unroll
        for (int off = 16; off; off >>= 1)
            #pragma unroll
            for (int j = 0; j < 17; j++)
                tA[j] += __shfl_down_sync(0xffffffffu, tA[j], off);
        if (lane == 0) {
            #pragma unroll
            for (int j = 0; j < 17; j++) red[w * 17 + j] = tA[j];
        }
    }
    __syncthreads();   // bitmap atomics + red visible

    if (tid < 17) {
        float s = 0.f;
        #pragma unroll
        for (int ww = 0; ww < 16; ww++) s += red[ww * 17 + tid];
        g_part[pair][0][tid] = s;
    }

    // ---- complement gather from L2: 20 jobs (h, word-half) over 16 warps ---
    #pragma unroll
    for (int rep = 0; rep < 2; rep++) {
        int j = w + rep * 16;
        if (j < 20) {
            int hh = j >> 1;
            int w0 = (j & 1) * 18;
            float cA[17];
            #pragma unroll
            for (int q = 0; q < 17; q++) cA[q] = 0.f;

            #pragma unroll 2
            for (int wd = w0; wd < w0 + 18; wd++) {
                unsigned bits = bm[hh * 36 + wd];     // broadcast LDS
                if (!((bits >> lane) & 1u)) {         // complement bit
                    int i = wd * 32 + lane;
                    float f[16];
                    load_row_g(gp, i, f);             // identical values to T-pass
                    float ss = 0.f;
                    #pragma unroll
                    for (int d = 0; d < Dc; d++) ss = fmaf(f[d], f[d], ss);
                    float vn = sqrt_approx(ss);
                    cA[16] += vn;
                    #pragma unroll
                    for (int d = 0; d < Dc; d++) cA[d] = fmaf(vn, f[d], cA[d]);
                }
            }
            #pragma unroll
            for (int off = 16; off; off >>= 1)
                #pragma unroll
                for (int q = 0; q < 17; q++)
                    cA[q] += __shfl_down_sync(0xffffffffu, cA[q], off);
            if (lane == 0) {
                #pragma unroll
                for (int q = 0; q < 17; q++) red2[j * 17 + q] = cA[q];
            }
        }
    }
    __syncthreads();

    // combine word-half jobs per h (fixed order)
    if (tid < Hc * 17) {
        int hh = tid / 17, q = tid - hh * 17;
        g_part[pair][1 + hh][q] = red2[(2 * hh) * 17 + q] + red2[(2 * hh + 1) * 17 + q];
    }
}

// ===== K2: per-chunk losses + last-CTA argmin/emit (K3 folded in) ==========
extern "C" __global__ void __launch_bounds__(K2_THR, 8)
k2_loss(const float* __restrict__ u, float* __restrict__ out)
{
    __shared__ float mu[Hc * Dc];
    __shared__ float mm[Hc];
    __shared__ float red[4 * Hc];
    __shared__ int   lastflag;

    const int o    = blockIdx.x;
    const int b    = blockIdx.y;
    const int ch   = blockIdx.z;
    const int pair = b * Oc + o;
    const int tid  = threadIdx.x;
    const int w    = tid >> 5;
    const int lane = tid & 31;

    // Mu[h][d] = (T - C_h) / (N - c_h)  (identical value in every CTA of pair)
    for (int t = tid; t < Hc * Dc; t += K2_THR) {
        int h = t >> 4, d = t & 15;
        float T = g_part[pair][0][d],     N = g_part[pair][0][16];
        float C = g_part[pair][1 + h][d], c = g_part[pair][1 + h][16];
        mu[t] = (T - C) / (N - c);
    }
    __syncthreads();
    if (tid < Hc) {
        float s = 0.f;
        #pragma unroll
        for (int d = 0; d < Dc; d++) s = fmaf(mu[tid * 16 + d], mu[tid * 16 + d], s);
        mm[tid] = s;
    }
    __syncthreads();

    // thread-per-row loss over this 128-row chunk (u is L2-hot from K1)
    float pl[Hc];
    #pragma unroll
    for (int h = 0; h < Hc; h++) pl[h] = 0.f;
    {
        const float4* gp = (const float4*)u + ((size_t)b * Ic * Oc + o) * 4;
        int i = ch * 128 + tid;
        float f[16];
        load_row_g(gp, i, f);
        float ss = 0.f;
        #pragma unroll
        for (int d = 0; d < Dc; d++) ss = fmaf(f[d], f[d], ss);

        #pragma unroll
        for (int h = 0; h < Hc; h++) {
            const float4* mp = (const float4*)&mu[h * 16];   // broadcast LDS.128
            float4 m0 = mp[0], m1 = mp[1], m2 = mp[2], m3 = mp[3];
            float dot = 0.f;
            dot = fmaf(f[0],  m0.x, dot); dot = fmaf(f[1],  m0.y, dot);
            dot = fmaf(f[2],  m0.z, dot); dot = fmaf(f[3],  m0.w, dot);
            dot = fmaf(f[4],  m1.x, dot); dot = fmaf(f[5],  m1.y, dot);
            dot = fmaf(f[6],  m1.z, dot); dot = fmaf(f[7],  m1.w, dot);
            dot = fmaf(f[8],  m2.x, dot); dot = fmaf(f[9],  m2.y, dot);
            dot = fmaf(f[10], m2.z, dot); dot = fmaf(f[11], m2.w, dot);
            dot = fmaf(f[12], m3.x, dot); dot = fmaf(f[13], m3.y, dot);
            dot = fmaf(f[14], m3.z, dot); dot = fmaf(f[15], m3.w, dot);
            float val = fmaf(-2.f, dot, ss + mm[h]);
            pl[h] += sqrt_approx(fmaxf(val, 0.f));
        }
    }
    #pragma unroll
    for (int off = 16; off; off >>= 1)
        #pragma unroll
        for (int h = 0; h < Hc; h++)
            pl[h] += __shfl_down_sync(0xffffffffu, pl[h], off);
    if (lane == 0) {
        #pragma unroll
        for (int h = 0; h < Hc; h++) red[w * Hc + h] = pl[h];
    }
    __syncthreads();

    if (tid < Hc) {
        float s = 0.f;
        #pragma unroll
        for (int ww = 0; ww < 4; ww++) s += red[ww * Hc + tid];
        g_loss[pair][ch][tid] = s;
    }
    __syncthreads();

    // ---- last-CTA-done: fold the final reduction + emit into this launch ---
    if (tid == 0) {
        __threadfence();                         // release our g_loss chunk
        int old = atomicAdd(&g_sem[pair], 1);
        lastflag = (old == NCHUNK - 1);
        if (lastflag) __threadfence();           // acquire all chunks
    }
    __syncthreads();

    if (lastflag) {
        if (tid == 0) g_sem[pair] = 0;           // reset for next graph replay
        if (w == 0) {
            float L = 3.0e38f;
            if (lane < Hc) {
                float s = 0.f;
                #pragma unroll
                for (int c = 0; c < NCHUNK; c++) s += g_loss[pair][c][lane];
                L = s;
            }
            // first-occurrence argmin across h (all lanes compute same result)
            int hm = 0;
            float best = __shfl_sync(0xffffffffu, L, 0);
            #pragma unroll
            for (int h = 1; h < Hc; h++) {
                float v = __shfl_sync(0xffffffffu, L, h);
                if (v < best) { best = v; hm = h; }
            }
            if (lane < Dc)
                out[(size_t)pair * Dc + lane] = mu[hm * Dc + lane];
        }
    }
}

extern "C" void kernel_launch(void* const* d_in, const int* in_sizes, int n_in,
                              void* d_out, int out_size)
{
    const float*        u    = (const float*)d_in[0];
    const unsigned int* sidx = (const unsigned int*)d_in[1];
    float*              out  = (float*)d_out;

    k1_partials<<<dim3(Oc, Bc), K1_THR>>>(u, sidx);
    k2_loss<<<dim3(Oc, Bc, NCHUNK), K2_THR>>>(u, out);
}